// round 3
// baseline (speedup 1.0000x reference)
#include <cuda_runtime.h>
#include <cstdint>

#define NB   16
#define SEQ  1024
#define DIM  512
#define NH   8
#define DH   64

// Scratch (allocation-free: __device__ globals)
// g_Q, g_K: [b,h,i,d-interleaved] tf32-rounded floats
// g_V:      [b,h,d,i-interleaved] tf32-rounded floats (transposed)
__device__ float g_Q[(size_t)NB*NH*SEQ*DH];
__device__ float g_K[(size_t)NB*NH*SEQ*DH];
__device__ float g_V[(size_t)NB*NH*DH*SEQ];
__device__ float g_AO[(size_t)NB*SEQ*DIM];

__device__ __forceinline__ uint32_t f2tf(float f) {
    uint32_t u;
    asm("cvt.rna.tf32.f32 %0, %1;" : "=r"(u) : "f"(f));
    return u;
}

__device__ __forceinline__ void mma8(float c[4], uint32_t a0, uint32_t a1,
                                     uint32_t a2, uint32_t a3,
                                     uint32_t b0, uint32_t b1) {
    asm volatile(
        "mma.sync.aligned.m16n8k8.row.col.f32.tf32.tf32.f32 "
        "{%0,%1,%2,%3}, {%4,%5,%6,%7}, {%8,%9}, {%0,%1,%2,%3};"
        : "+f"(c[0]), "+f"(c[1]), "+f"(c[2]), "+f"(c[3])
        : "r"(a0), "r"(a1), "r"(a2), "r"(a3), "r"(b0), "r"(b1));
}

__device__ __forceinline__ void cp16(uint32_t dst, const void* src) {
    asm volatile("cp.async.cg.shared.global [%0], [%1], 16;" :: "r"(dst), "l"(src));
}

// interleave within 8-groups so (k, k+4) become adjacent pair at position 2k'
__device__ __forceinline__ int ilv8(int k) {
    return (k & ~7) | ((k & 3) << 1) | ((k >> 2) & 1);
}

// ---------------------------------------------------------------------------
// GEMM: Y = X @ W^T.  BM=128, BN=128, BK=32; 256 threads = 8 warps (4m x 2n),
// warp tile 32x64.  smem pitch 40, k-interleaved -> all frag loads are LDS.64.
// mode 0: Y=g_Q [b,h,i,ilv(d)] *scale, tf32-rounded
// mode 1: Y=g_K [b,h,i,ilv(d)], tf32
// mode 2: Y=g_V [b,h,d,ilv(i)], tf32 (transposed)
// mode 3: Y=Yplain [m,col] fp32.   X==nullptr -> read g_AO.
// ---------------------------------------------------------------------------
__global__ void __launch_bounds__(256) proj_kernel(
    const float* __restrict__ X, const float* __restrict__ W,
    float* __restrict__ Yplain, int mode, float scale)
{
    __shared__ uint32_t As[128*40];
    __shared__ uint32_t Bs[128*40];

    const float* __restrict__ Xp = X ? X : g_AO;
    const int tid  = threadIdx.x;
    const int lane = tid & 31, warp = tid >> 5;
    const int q    = lane & 3, l4 = lane >> 2;
    const int wm   = warp >> 1, wn = warp & 1;
    const int m0   = blockIdx.y << 7;
    const int c0   = blockIdx.x << 7;

    float acc[2][8][4] = {};

    for (int k0 = 0; k0 < DIM; k0 += 32) {
        __syncthreads();
        #pragma unroll
        for (int t = 0; t < 4; t++) {
            const int f   = tid + t*256;
            const int row = f >> 3, c4 = (f & 7) << 2;
            const int gb  = (c4 & ~7) + ((c4 >> 2) & 1);   // group base + half-bit
            const float4 xa = *(const float4*)&Xp[(size_t)(m0+row)*DIM + k0 + c4];
            As[row*40 + gb + 0] = f2tf(xa.x);
            As[row*40 + gb + 2] = f2tf(xa.y);
            As[row*40 + gb + 4] = f2tf(xa.z);
            As[row*40 + gb + 6] = f2tf(xa.w);
            const float4 wb = *(const float4*)&W[(size_t)(c0+row)*DIM + k0 + c4];
            Bs[row*40 + gb + 0] = f2tf(wb.x);
            Bs[row*40 + gb + 2] = f2tf(wb.y);
            Bs[row*40 + gb + 4] = f2tf(wb.z);
            Bs[row*40 + gb + 6] = f2tf(wb.w);
        }
        __syncthreads();

        #pragma unroll
        for (int ks = 0; ks < 4; ks++) {
            const int ko = ks << 3;
            uint2 a0[2], a1[2];
            #pragma unroll
            for (int mt = 0; mt < 2; mt++) {
                const int r = wm*32 + mt*16 + l4;
                a0[mt] = *(const uint2*)&As[r*40     + ko + 2*q];
                a1[mt] = *(const uint2*)&As[(r+8)*40 + ko + 2*q];
            }
            #pragma unroll
            for (int nt = 0; nt < 8; nt++) {
                const int n = wn*64 + nt*8 + l4;
                const uint2 bv = *(const uint2*)&Bs[n*40 + ko + 2*q];
                mma8(acc[0][nt], a0[0].x, a1[0].x, a0[0].y, a1[0].y, bv.x, bv.y);
                mma8(acc[1][nt], a0[1].x, a1[1].x, a0[1].y, a1[1].y, bv.x, bv.y);
            }
        }
    }

    float* __restrict__ Ysc = (mode == 0) ? g_Q : (mode == 1) ? g_K : g_V;
    #pragma unroll
    for (int mt = 0; mt < 2; mt++) {
        #pragma unroll
        for (int half = 0; half < 2; half++) {
            const int m  = m0 + wm*32 + mt*16 + half*8 + l4;
            const int bb = m >> 10, i = m & (SEQ-1);
            #pragma unroll
            for (int nt = 0; nt < 8; nt++) {
                const int col = c0 + wn*64 + nt*8 + 2*q;
                const float v0 = acc[mt][nt][half*2 + 0] * scale;
                const float v1 = acc[mt][nt][half*2 + 1] * scale;
                if (mode == 3) {
                    *(float2*)&Yplain[(size_t)m*DIM + col] = make_float2(v0, v1);
                } else {
                    const int h = col >> 6, d = col & 63;
                    if (mode == 2) {   // V^T: [b,h,d, ilv(i)]
                        const size_t base = ((size_t)(bb*NH + h)*DH + d)*SEQ + ilv8(i);
                        Ysc[base]       = __uint_as_float(f2tf(v0));
                        Ysc[base + SEQ] = __uint_as_float(f2tf(v1));
                    } else {           // Q/K: [b,h,i, ilv(d)]
                        const size_t base = ((size_t)(bb*NH + h)*SEQ + i)*DH;
                        Ysc[base + ilv8(d)]   = __uint_as_float(f2tf(v0));
                        Ysc[base + ilv8(d+1)] = __uint_as_float(f2tf(v1));
                    }
                }
            }
        }
    }
}

// ---------------------------------------------------------------------------
// Flash attention, tf32 mma.  Block = (b, h, 128-query tile); 128 threads =
// 4 warps, each warp owns 32 query rows (two m16 frags). KV tiles of 64.
// Q frags in registers; K/V staged by cp.async (pre-formatted by proj);
// bias gmem->regs; P per-warp smem stripe, XOR-swizzled, all frags LDS.64.
// smem: Ks[64][72], Vs[64][72] (V^T), Ps[128][72]  = 73,728 B.
// ---------------------------------------------------------------------------
__global__ void __launch_bounds__(128, 2) attn_kernel(const float* __restrict__ bias)
{
    extern __shared__ uint32_t sm[];
    uint32_t* Ksm = sm;             // 64*72
    uint32_t* Vsm = sm + 64*72;     // 64*72
    uint32_t* Psm = sm + 2*64*72;   // 128*72
    const uint32_t smem_b = (uint32_t)__cvta_generic_to_shared(sm);
    const uint32_t ks_b = smem_b, vs_b = smem_b + 64*72*4;

    const int tid  = threadIdx.x;
    const int lane = tid & 31, warp = tid >> 5;
    const int q    = lane & 3, l4 = lane >> 2;
    const int b    = blockIdx.z, h = blockIdx.y;
    const int i0   = blockIdx.x << 7;
    const int W0   = warp << 5;
    const int bx   = (l4 >> 2) & 1;          // P swizzle bit
    const int qx   = q ^ bx;

    const float* __restrict__ Qg = g_Q + ((size_t)(b*NH + h)*SEQ + i0)*DH;
    const float* __restrict__ Kg = g_K + (size_t)(b*NH + h)*SEQ*DH;
    const float* __restrict__ Vg = g_V + (size_t)(b*NH + h)*DH*SEQ;
    const float* __restrict__ Bh = bias + (size_t)h*SEQ*SEQ + (size_t)i0*SEQ;

    // Q fragments -> registers (held for all 16 KV iterations)
    uint2 qf0[2][8], qf1[2][8];
    #pragma unroll
    for (int mt = 0; mt < 2; mt++)
        #pragma unroll
        for (int ks = 0; ks < 8; ks++) {
            const int r = W0 + mt*16 + l4;
            qf0[mt][ks] = *(const uint2*)&Qg[(size_t)r*DH     + ks*8 + 2*q];
            qf1[mt][ks] = *(const uint2*)&Qg[(size_t)(r+8)*DH + ks*8 + 2*q];
        }

    float o[2][8][4] = {};
    float mr[2][2] = {{-1e30f,-1e30f},{-1e30f,-1e30f}};
    float lr[2][2] = {};

    for (int j0 = 0; j0 < SEQ; j0 += 64) {
        __syncthreads();   // prev tile's K/V consumers done before overwrite
        #pragma unroll
        for (int t = 0; t < 8; t++) {
            const int f = tid + t*128;
            const int row = f >> 4, c4 = (f & 15) << 2;
            cp16(ks_b + (row*72 + c4)*4, Kg + (size_t)(j0+row)*DH + c4);
            cp16(vs_b + (row*72 + c4)*4, Vg + (size_t)row*SEQ + j0 + c4);
        }
        asm volatile("cp.async.commit_group;");

        // bias -> s (c-fragment layout), overlapped with cp.async
        float s[2][8][4];
        #pragma unroll
        for (int mt = 0; mt < 2; mt++)
            #pragma unroll
            for (int nt = 0; nt < 8; nt++) {
                const int r = W0 + mt*16 + l4;
                const float2 b0 = *(const float2*)&Bh[(size_t)r*SEQ     + j0 + nt*8 + 2*q];
                const float2 b1 = *(const float2*)&Bh[(size_t)(r+8)*SEQ + j0 + nt*8 + 2*q];
                s[mt][nt][0]=b0.x; s[mt][nt][1]=b0.y; s[mt][nt][2]=b1.x; s[mt][nt][3]=b1.y;
            }

        asm volatile("cp.async.wait_group 0;");
        __syncthreads();

        // S += Q K^T
        #pragma unroll
        for (int ks = 0; ks < 8; ks++) {
            #pragma unroll
            for (int nt = 0; nt < 8; nt++) {
                const uint2 bv = *(const uint2*)&Ksm[(nt*8 + l4)*72 + ks*8 + 2*q];
                mma8(s[0][nt], qf0[0][ks].x, qf1[0][ks].x, qf0[0][ks].y, qf1[0][ks].y, bv.x, bv.y);
                mma8(s[1][nt], qf0[1][ks].x, qf1[1][ks].x, qf0[1][ks].y, qf1[1][ks].y, bv.x, bv.y);
            }
        }

        // online softmax (4 row-groups; stats within quads)
        #pragma unroll
        for (int mt = 0; mt < 2; mt++)
            #pragma unroll
            for (int half = 0; half < 2; half++) {
                float rm = -1e30f;
                #pragma unroll
                for (int nt = 0; nt < 8; nt++)
                    rm = fmaxf(rm, fmaxf(s[mt][nt][half*2], s[mt][nt][half*2+1]));
                rm = fmaxf(rm, __shfl_xor_sync(0xffffffffu, rm, 1));
                rm = fmaxf(rm, __shfl_xor_sync(0xffffffffu, rm, 2));
                const float nm   = fmaxf(mr[mt][half], rm);
                const float corr = __expf(mr[mt][half] - nm);
                mr[mt][half] = nm;
                float rs = 0.f;
                #pragma unroll
                for (int nt = 0; nt < 8; nt++) {
                    const float p0 = __expf(s[mt][nt][half*2]   - nm);
                    const float p1 = __expf(s[mt][nt][half*2+1] - nm);
                    s[mt][nt][half*2] = p0; s[mt][nt][half*2+1] = p1;
                    rs += p0 + p1;
                }
                rs += __shfl_xor_sync(0xffffffffu, rs, 1);
                rs += __shfl_xor_sync(0xffffffffu, rs, 2);
                lr[mt][half] = lr[mt][half]*corr + rs;
                #pragma unroll
                for (int nt = 0; nt < 8; nt++) {
                    o[mt][nt][half*2]   *= corr;
                    o[mt][nt][half*2+1] *= corr;
                }
            }

        // P -> per-warp smem stripe (interleaved + XOR swizzle)
        const int p0 = ((2*q) & 3)*2 + (q >> 1);       // pos(2q)
        const int c0w = p0 ^ (bx << 1);
        const int c1w = (p0 + 2) ^ (bx << 1);
        #pragma unroll
        for (int mt = 0; mt < 2; mt++) {
            const int r = W0 + mt*16 + l4;
            #pragma unroll
            for (int nt = 0; nt < 8; nt++) {
                Psm[r*72     + nt*8 + c0w] = f2tf(s[mt][nt][0]);
                Psm[r*72     + nt*8 + c1w] = f2tf(s[mt][nt][1]);
                Psm[(r+8)*72 + nt*8 + c0w] = f2tf(s[mt][nt][2]);
                Psm[(r+8)*72 + nt*8 + c1w] = f2tf(s[mt][nt][3]);
            }
        }
        __syncwarp();

        // O += P @ V
        #pragma unroll
        for (int ks = 0; ks < 8; ks++) {
            uint2 pa0[2], pa1[2];
            #pragma unroll
            for (int mt = 0; mt < 2; mt++) {
                const int r = W0 + mt*16 + l4;
                pa0[mt] = *(const uint2*)&Psm[r*72     + ks*8 + 2*qx];
                pa1[mt] = *(const uint2*)&Psm[(r+8)*72 + ks*8 + 2*qx];
            }
            #pragma unroll
            for (int nt = 0; nt < 8; nt++) {
                const uint2 vv = *(const uint2*)&Vsm[(nt*8 + l4)*72 + ks*8 + 2*q];
                mma8(o[0][nt], pa0[0].x, pa1[0].x, pa0[0].y, pa1[0].y, vv.x, vv.y);
                mma8(o[1][nt], pa0[1].x, pa1[1].x, pa0[1].y, pa1[1].y, vv.x, vv.y);
            }
        }
    }

    // normalize + write [b, n, h*64+d] for the O projection
    #pragma unroll
    for (int mt = 0; mt < 2; mt++)
        #pragma unroll
        for (int half = 0; half < 2; half++) {
            const float inv = 1.f / lr[mt][half];
            const int gi = i0 + W0 + mt*16 + half*8 + l4;
            #pragma unroll
            for (int nt = 0; nt < 8; nt++) {
                const int d = nt*8 + 2*q;
                *(float2*)&g_AO[((size_t)b*SEQ + gi)*DIM + h*DH + d] =
                    make_float2(o[mt][nt][half*2]*inv, o[mt][nt][half*2+1]*inv);
            }
        }
}

// ---------------------------------------------------------------------------
extern "C" void kernel_launch(void* const* d_in, const int* in_sizes, int n_in,
                              void* d_out, int out_size)
{
    const float* x    = (const float*)d_in[0];
    const float* bias = (const float*)d_in[1];
    const float* Wq   = (const float*)d_in[2];
    const float* Wk   = (const float*)d_in[3];
    const float* Wv   = (const float*)d_in[4];
    const float* Wo   = (const float*)d_in[5];
    float* out = (float*)d_out;

    const dim3 pgrid(DIM/128, (NB*SEQ)/128);   // (4, 128)
    proj_kernel<<<pgrid, 256>>>(x, Wq, nullptr, 0, 0.125f);  // Q * DH^-0.5
    proj_kernel<<<pgrid, 256>>>(x, Wk, nullptr, 1, 1.0f);
    proj_kernel<<<pgrid, 256>>>(x, Wv, nullptr, 2, 1.0f);

    const int smem = (64*72 + 64*72 + 128*72) * (int)sizeof(uint32_t);  // 73,728 B
    cudaFuncSetAttribute(attn_kernel, cudaFuncAttributeMaxDynamicSharedMemorySize, smem);
    attn_kernel<<<dim3(SEQ/128, NH, NB), 128, smem>>>(bias);

    proj_kernel<<<pgrid, 256>>>(nullptr, Wo, out, 3, 1.0f);
}